// round 10
// baseline (speedup 1.0000x reference)
#include <cuda_runtime.h>
#include <math.h>
#include <float.h>

// Problem dims
#define Bn   8
#define N1D  256
#define N2D  256
#define FD   128
#define ROWS (Bn * N1D)          // 2048
#define KD   128

// GEMM tiling: 64x64 tile per 256-thread CTA, 8x2 microtile, f32x2-packed.
#define RT  64
#define CT  64
#define LDP 132                  // floats per kp-row (64 entities x 2 + pad)

// ---------------- device scratch (no allocations allowed) ----------------
__device__ float g_Mx2[Bn * N2D * FD];       // M(x2)            [2048,128]
__device__ float g_m1 [ROWS * FD];           // W(x1)            [2048,128]
__device__ float g_gh [ROWS * 3 * FD];       // x1 @ whh^T + bhh [2048,384]
__device__ float g_x  [ROWS * FD];           // relu(m1+m2)      [2048,128]
__device__ float g_gi [ROWS * 3 * FD];       // x @ wih^T + bih  [2048,384]
__device__ int   g_cnt [ROWS];               // valid-edge counts
__device__ int   g_list[ROWS * N2D];         // valid-edge j lists

// Packed dual-FMA: d.lo += a.lo*b.lo; d.hi += a.hi*b.hi  (Blackwell FFMA2)
__device__ __forceinline__ void ffma2(unsigned long long& d,
                                      unsigned long long a,
                                      unsigned long long b)
{
    asm("fma.rn.f32x2 %0, %1, %2, %0;" : "+l"(d) : "l"(a), "l"(b));
}

union U64F2 { unsigned long long u; float2 f; };

// ---------------- 64x64 SGEMM tile, f32x2-packed ---------------------------
// Smem layout: S[kp][e*2 + p] where kp=k/2, p=k&1, e = row/col index 0..63.
// Inner loop per kp: 4x LDS.128 a (broadcast) + 1x LDS.128 w (coalesced)
// + 16 FFMA2. Accumulators pack (even-k, odd-k) partials; summed at the end.
__device__ __forceinline__ void gemm_tile(
    const float* __restrict__ A, const float* __restrict__ W,
    const float* __restrict__ b,
    float* __restrict__ C, int ldC, int rowbase, int colbase, float* sm)
{
    float* As = sm;                   // [64 kp][LDP]
    float* Ws = sm + 64 * LDP;        // [64 kp][LDP]
    const int tid  = threadIdx.x;
    const int lane = tid & 31, warp = tid >> 5;
    const int kq = lane & 3;
    const int rr = lane >> 2;
    const int e  = warp * 8 + rr;     // entity (row for A, col for W), 0..63

    // Stage with k-pair interleave: (k0,k1) adjacent at [k/2][e*2].
#pragma unroll
    for (int it = 0; it < 8; it++) {
        int kk = it * 4 + kq;         // float4 index along k, 0..31
        float4 av = *(const float4*)(A + (size_t)(rowbase + e) * KD + kk * 4);
        *(float2*)(As + (2 * kk)     * LDP + 2 * e) = make_float2(av.x, av.y);
        *(float2*)(As + (2 * kk + 1) * LDP + 2 * e) = make_float2(av.z, av.w);
        float4 wv = *(const float4*)(W + (size_t)(colbase + e) * KD + kk * 4);
        *(float2*)(Ws + (2 * kk)     * LDP + 2 * e) = make_float2(wv.x, wv.y);
        *(float2*)(Ws + (2 * kk + 1) * LDP + 2 * e) = make_float2(wv.z, wv.w);
    }
    __syncthreads();

    const int rg = tid >> 5;          // 8 row groups x 8 rows
    const int cg = tid & 31;          // 32 col groups x 2 cols

    unsigned long long acc[8][2];
#pragma unroll
    for (int i = 0; i < 8; i++) { acc[i][0] = 0ull; acc[i][1] = 0ull; }

    const float* ap = As + rg * 16;   // rows rg*8.., x-offset = row*2
    const float* wp = Ws + cg * 4;    // cols cg*2.., x-offset = col*2

#pragma unroll 4
    for (int kp = 0; kp < 64; kp++) {
        const float* ab = ap + kp * LDP;
        ulonglong2 a01 = *(const ulonglong2*)(ab);       // rows 0,1 k-pairs
        ulonglong2 a23 = *(const ulonglong2*)(ab + 4);   // rows 2,3
        ulonglong2 a45 = *(const ulonglong2*)(ab + 8);   // rows 4,5
        ulonglong2 a67 = *(const ulonglong2*)(ab + 12);  // rows 6,7
        ulonglong2 wv  = *(const ulonglong2*)(wp + kp * LDP);  // cols 0,1
        ffma2(acc[0][0], a01.x, wv.x); ffma2(acc[0][1], a01.x, wv.y);
        ffma2(acc[1][0], a01.y, wv.x); ffma2(acc[1][1], a01.y, wv.y);
        ffma2(acc[2][0], a23.x, wv.x); ffma2(acc[2][1], a23.x, wv.y);
        ffma2(acc[3][0], a23.y, wv.x); ffma2(acc[3][1], a23.y, wv.y);
        ffma2(acc[4][0], a45.x, wv.x); ffma2(acc[4][1], a45.x, wv.y);
        ffma2(acc[5][0], a45.y, wv.x); ffma2(acc[5][1], a45.y, wv.y);
        ffma2(acc[6][0], a67.x, wv.x); ffma2(acc[6][1], a67.x, wv.y);
        ffma2(acc[7][0], a67.y, wv.x); ffma2(acc[7][1], a67.y, wv.y);
    }

    float2 bv = *(const float2*)(b + colbase + cg * 2);
#pragma unroll
    for (int i = 0; i < 8; i++) {
        U64F2 u0, u1;
        u0.u = acc[i][0];
        u1.u = acc[i][1];
        float2 o;
        o.x = u0.f.x + u0.f.y + bv.x;
        o.y = u1.f.x + u1.f.y + bv.y;
        *(float2*)(C + (size_t)(rowbase + rg * 8 + i) * ldC + colbase + cg * 2) = o;
    }
}

// Edge-list compaction for 8 rows (one warp per row).
__device__ __forceinline__ void lists_block(const float* __restrict__ ve, int rowblock)
{
    int w = threadIdx.x >> 5, lane = threadIdx.x & 31;
    int row = rowblock * 8 + w;
    const float* mrow = ve + (size_t)row * N2D;
    int base = 0;
#pragma unroll
    for (int r = 0; r < 8; r++) {
        int j = r * 32 + lane;
        float v = mrow[j];
        unsigned bal = __ballot_sync(0xffffffffu, v != 0.0f);
        if (v != 0.0f)
            g_list[(size_t)row * N2D + base + __popc(bal & ((1u << lane) - 1u))] = j;
        base += __popc(bal);
    }
    if (lane == 0) g_cnt[row] = base;
}

// Phase 1 (576 blocks): [0,64) Mx2, [64,128) m1, [128,320) gh, [320,576) lists
__global__ void __launch_bounds__(256, 3) k_p1(
    const float* __restrict__ x1, const float* __restrict__ x2,
    const float* __restrict__ ve,
    const float* __restrict__ W_w, const float* __restrict__ W_b,
    const float* __restrict__ M_w, const float* __restrict__ M_b,
    const float* __restrict__ whh, const float* __restrict__ bhh)
{
    extern __shared__ float sm[];
    int bid = blockIdx.x;
    if (bid < 64) {
        gemm_tile(x2, M_w, M_b, g_Mx2, FD, (bid & 31) * RT, (bid >> 5) * CT, sm);
    } else if (bid < 128) {
        int t = bid - 64;
        gemm_tile(x1, W_w, W_b, g_m1, FD, (t & 31) * RT, (t >> 5) * CT, sm);
    } else if (bid < 320) {
        int t = bid - 128;
        gemm_tile(x1, whh, bhh, g_gh, 3 * FD, (t & 31) * RT, (t >> 5) * CT, sm);
    } else {
        lists_block(ve, bid - 320);
    }
}

// gi = x @ wih^T + bih  (64x64 tiles, occ 3)
__global__ void __launch_bounds__(256, 3) k_gemmGI(
    const float* __restrict__ wih, const float* __restrict__ bih)
{
    extern __shared__ float sm[];
    gemm_tile(g_x, wih, bih, g_gi, 3 * FD, blockIdx.x * RT, blockIdx.y * CT, sm);
}

// ---------------- sparse masked max + relu(m1 + m2) — R7 proven ------------
__device__ __forceinline__ float4 max4(float4 a, float4 b) {
    float4 r;
    r.x = fmaxf(a.x, b.x); r.y = fmaxf(a.y, b.y);
    r.z = fmaxf(a.z, b.z); r.w = fmaxf(a.w, b.w);
    return r;
}

__global__ void __launch_bounds__(256) k_maskmax()
{
    int warp = threadIdx.x >> 5, lane = threadIdx.x & 31;
    int row = blockIdx.x * 8 + warp;
    int b = row >> 8;
    const float4* __restrict__ Mb = (const float4*)(g_Mx2 + (size_t)b * N2D * FD);
    const int* __restrict__ lst = g_list + (size_t)row * N2D;
    int cnt = g_cnt[row];

    float4 m = make_float4(-FLT_MAX, -FLT_MAX, -FLT_MAX, -FLT_MAX);
    int t = 0;
    for (; t + 4 <= cnt; t += 4) {
        int j0 = __ldg(lst + t),     j1 = __ldg(lst + t + 1);
        int j2 = __ldg(lst + t + 2), j3 = __ldg(lst + t + 3);
        float4 v0 = Mb[j0 * 32 + lane];
        float4 v1 = Mb[j1 * 32 + lane];
        float4 v2 = Mb[j2 * 32 + lane];
        float4 v3 = Mb[j3 * 32 + lane];
        m = max4(m, max4(max4(v0, v1), max4(v2, v3)));
    }
    for (; t < cnt; t++)
        m = max4(m, Mb[__ldg(lst + t) * 32 + lane]);
    if (cnt < N2D) {
        float4 z = make_float4(0.f, 0.f, 0.f, 0.f);
        m = max4(m, z);
    }
    float4 m1v = ((const float4*)g_m1)[row * 32 + lane];
    float4 x;
    x.x = fmaxf(m1v.x + m.x, 0.f);
    x.y = fmaxf(m1v.y + m.y, 0.f);
    x.z = fmaxf(m1v.z + m.z, 0.f);
    x.w = fmaxf(m1v.w + m.w, 0.f);
    ((float4*)g_x)[row * 32 + lane] = x;
}

// ---------------- GRU gates (fast approx, float4) --------------------------
__device__ __forceinline__ float sigf(float t) {
    return __fdividef(1.0f, 1.0f + __expf(-t));
}
__device__ __forceinline__ float tanh_approx(float t) {
    float y;
    asm("tanh.approx.f32 %0, %1;" : "=f"(y) : "f"(t));
    return y;
}

__global__ void __launch_bounds__(128) k_gates(
    const float* __restrict__ x1, float* __restrict__ out)
{
    int idx = blockIdx.x * 128 + threadIdx.x;   // one float4 (4 feats)
    int row = idx >> 5, fq = idx & 31;
    const float4* gi = (const float4*)(g_gi + (size_t)row * 384);
    const float4* gh = (const float4*)(g_gh + (size_t)row * 384);
    float4 ir = __ldg(gi + fq);
    float4 iz = __ldg(gi + 32 + fq);
    float4 in_ = __ldg(gi + 64 + fq);
    float4 hr = __ldg(gh + fq);
    float4 hz = __ldg(gh + 32 + fq);
    float4 hn = __ldg(gh + 64 + fq);
    float4 hp = __ldg((const float4*)x1 + idx);
    float4 o;
    {
        float r = sigf(ir.x + hr.x), z = sigf(iz.x + hz.x);
        float n = tanh_approx(in_.x + r * hn.x);
        o.x = (1.0f - z) * n + z * hp.x;
    }
    {
        float r = sigf(ir.y + hr.y), z = sigf(iz.y + hz.y);
        float n = tanh_approx(in_.y + r * hn.y);
        o.y = (1.0f - z) * n + z * hp.y;
    }
    {
        float r = sigf(ir.z + hr.z), z = sigf(iz.z + hz.z);
        float n = tanh_approx(in_.z + r * hn.z);
        o.z = (1.0f - z) * n + z * hp.z;
    }
    {
        float r = sigf(ir.w + hr.w), z = sigf(iz.w + hz.w);
        float n = tanh_approx(in_.w + r * hn.w);
        o.w = (1.0f - z) * n + z * hp.w;
    }
    ((float4*)out)[idx] = o;
}

// ---------------- launch ---------------------------------------------------
extern "C" void kernel_launch(void* const* d_in, const int* in_sizes, int n_in,
                              void* d_out, int out_size)
{
    const float* x1  = (const float*)d_in[0];
    const float* x2  = (const float*)d_in[1];
    const float* ve  = (const float*)d_in[2];
    const float* W_w = (const float*)d_in[3];
    const float* W_b = (const float*)d_in[4];
    const float* M_w = (const float*)d_in[5];
    const float* M_b = (const float*)d_in[6];
    const float* wih = (const float*)d_in[7];
    const float* whh = (const float*)d_in[8];
    const float* bih = (const float*)d_in[9];
    const float* bhh = (const float*)d_in[10];
    float* out = (float*)d_out;

    const int smem = 2 * 64 * LDP * (int)sizeof(float);   // 67584 B
    cudaFuncSetAttribute(k_p1,     cudaFuncAttributeMaxDynamicSharedMemorySize, smem);
    cudaFuncSetAttribute(k_gemmGI, cudaFuncAttributeMaxDynamicSharedMemorySize, smem);

    k_p1<<<576, 256, smem>>>(x1, x2, ve, W_w, W_b, M_w, M_b, whh, bhh);
    k_maskmax<<<ROWS / 8, 256>>>();
    k_gemmGI<<<dim3(ROWS / RT, 6), 256, smem>>>(wih, bih);
    k_gates<<<(ROWS * FD / 4) / 128, 128>>>(x1, out);
}

// round 11
// speedup vs baseline: 1.2338x; 1.2338x over previous
#include <cuda_runtime.h>
#include <math.h>
#include <float.h>

// Problem dims
#define Bn   8
#define N1D  256
#define N2D  256
#define FD   128
#define ROWS (Bn * N1D)          // 2048
#define KD   128

// GEMM tiling: 64x64 tile per 256-thread CTA, 4x4 microtile (R7 proven).
#define RT  64
#define CT  64
#define LDT 68                   // padded minor dim of [k][*] smem tiles

// ---------------- device scratch (no allocations allowed) ----------------
__device__ float g_Mx2[Bn * N2D * FD];       // M(x2)            [2048,128]
__device__ float g_m1 [ROWS * FD];           // W(x1)            [2048,128]
__device__ float g_gh [ROWS * 3 * FD];       // x1 @ whh^T + bhh [2048,384]
__device__ float g_x  [ROWS * FD];           // relu(m1+m2)      [2048,128]
__device__ float g_gi [ROWS * 3 * FD];       // x @ wih^T + bih  [2048,384]
__device__ int   g_cnt [ROWS];               // valid-edge counts
__device__ int   g_list[ROWS * N2D];         // valid-edge j lists

// ---------------- 64x64 SGEMM tile (R7 proven) -----------------------------
__device__ __forceinline__ void gemm_tile(
    const float* __restrict__ A, const float* __restrict__ W,
    const float* __restrict__ b,
    float* __restrict__ C, int ldC, int rowbase, int colbase, float* sm)
{
    float* As = sm;                   // [KD][LDT]
    float* Ws = sm + KD * LDT;        // [KD][LDT]
    const int tid  = threadIdx.x;
    const int lane = tid & 31, warp = tid >> 5;
    const int kq = lane & 3;
    const int rr = lane >> 2;
    const int r  = warp * 8 + rr;     // 0..63

#pragma unroll
    for (int it = 0; it < 8; it++) {
        int kk = it * 4 + kq;
        float4 av = *(const float4*)(A + (size_t)(rowbase + r) * KD + kk * 4);
        As[(kk * 4 + 0) * LDT + r] = av.x;
        As[(kk * 4 + 1) * LDT + r] = av.y;
        As[(kk * 4 + 2) * LDT + r] = av.z;
        As[(kk * 4 + 3) * LDT + r] = av.w;
        float4 wv = *(const float4*)(W + (size_t)(colbase + r) * KD + kk * 4);
        Ws[(kk * 4 + 0) * LDT + r] = wv.x;
        Ws[(kk * 4 + 1) * LDT + r] = wv.y;
        Ws[(kk * 4 + 2) * LDT + r] = wv.z;
        Ws[(kk * 4 + 3) * LDT + r] = wv.w;
    }
    __syncthreads();

    const int cg = tid & 15;
    const int rg = tid >> 4;

    float acc[4][4];
#pragma unroll
    for (int i = 0; i < 4; i++)
#pragma unroll
        for (int j = 0; j < 4; j++) acc[i][j] = 0.0f;

    const float* ap = As + rg * 4;
    const float* wp = Ws + cg * 4;

#pragma unroll 8
    for (int k = 0; k < KD; k++) {
        float4 a = *(const float4*)(ap + k * LDT);
        float4 w = *(const float4*)(wp + k * LDT);
        acc[0][0] += a.x * w.x; acc[0][1] += a.x * w.y; acc[0][2] += a.x * w.z; acc[0][3] += a.x * w.w;
        acc[1][0] += a.y * w.x; acc[1][1] += a.y * w.y; acc[1][2] += a.y * w.z; acc[1][3] += a.y * w.w;
        acc[2][0] += a.z * w.x; acc[2][1] += a.z * w.y; acc[2][2] += a.z * w.z; acc[2][3] += a.z * w.w;
        acc[3][0] += a.w * w.x; acc[3][1] += a.w * w.y; acc[3][2] += a.w * w.z; acc[3][3] += a.w * w.w;
    }

    float4 bv = *(const float4*)(b + colbase + cg * 4);
#pragma unroll
    for (int i = 0; i < 4; i++) {
        float4 o;
        o.x = acc[i][0] + bv.x;
        o.y = acc[i][1] + bv.y;
        o.z = acc[i][2] + bv.z;
        o.w = acc[i][3] + bv.w;
        *(float4*)(C + (size_t)(rowbase + rg * 4 + i) * ldC + colbase + cg * 4) = o;
    }
}

// Edge-list compaction for 8 rows (one warp per row).
__device__ __forceinline__ void lists_block(const float* __restrict__ ve, int rowblock)
{
    int w = threadIdx.x >> 5, lane = threadIdx.x & 31;
    int row = rowblock * 8 + w;
    const float* mrow = ve + (size_t)row * N2D;
    int base = 0;
#pragma unroll
    for (int r = 0; r < 8; r++) {
        int j = r * 32 + lane;
        float v = mrow[j];
        unsigned bal = __ballot_sync(0xffffffffu, v != 0.0f);
        if (v != 0.0f)
            g_list[(size_t)row * N2D + base + __popc(bal & ((1u << lane) - 1u))] = j;
        base += __popc(bal);
    }
    if (lane == 0) g_cnt[row] = base;
}

// ---------------- masked-max block body (R7 proven) ------------------------
__device__ __forceinline__ float4 max4(float4 a, float4 b) {
    float4 r;
    r.x = fmaxf(a.x, b.x); r.y = fmaxf(a.y, b.y);
    r.z = fmaxf(a.z, b.z); r.w = fmaxf(a.w, b.w);
    return r;
}

__device__ __forceinline__ void maskmax_block(int blk)
{
    int warp = threadIdx.x >> 5, lane = threadIdx.x & 31;
    int row = blk * 8 + warp;
    int b = row >> 8;
    const float4* __restrict__ Mb = (const float4*)(g_Mx2 + (size_t)b * N2D * FD);
    const int* __restrict__ lst = g_list + (size_t)row * N2D;
    int cnt = g_cnt[row];

    float4 m = make_float4(-FLT_MAX, -FLT_MAX, -FLT_MAX, -FLT_MAX);
    int t = 0;
    for (; t + 4 <= cnt; t += 4) {
        int j0 = __ldg(lst + t),     j1 = __ldg(lst + t + 1);
        int j2 = __ldg(lst + t + 2), j3 = __ldg(lst + t + 3);
        float4 v0 = Mb[j0 * 32 + lane];
        float4 v1 = Mb[j1 * 32 + lane];
        float4 v2 = Mb[j2 * 32 + lane];
        float4 v3 = Mb[j3 * 32 + lane];
        m = max4(m, max4(max4(v0, v1), max4(v2, v3)));
    }
    for (; t < cnt; t++)
        m = max4(m, Mb[__ldg(lst + t) * 32 + lane]);
    if (cnt < N2D) {   // masked-out entries contribute exact 0
        float4 z = make_float4(0.f, 0.f, 0.f, 0.f);
        m = max4(m, z);
    }
    float4 m1v = ((const float4*)g_m1)[row * 32 + lane];
    float4 x;
    x.x = fmaxf(m1v.x + m.x, 0.f);
    x.y = fmaxf(m1v.y + m.y, 0.f);
    x.z = fmaxf(m1v.z + m.z, 0.f);
    x.w = fmaxf(m1v.w + m.w, 0.f);
    ((float4*)g_x)[row * 32 + lane] = x;
}

// Phase 1a (384 blocks): [0,64) Mx2, [64,128) m1, [128,384) edge lists.
// Only the producers maskmax actually depends on — gh is deferred to k_mix.
__global__ void __launch_bounds__(256, 3) k_p1a(
    const float* __restrict__ x1, const float* __restrict__ x2,
    const float* __restrict__ ve,
    const float* __restrict__ W_w, const float* __restrict__ W_b,
    const float* __restrict__ M_w, const float* __restrict__ M_b)
{
    extern __shared__ float sm[];
    int bid = blockIdx.x;
    if (bid < 64) {
        gemm_tile(x2, M_w, M_b, g_Mx2, FD, (bid & 31) * RT, (bid >> 5) * CT, sm);
    } else if (bid < 128) {
        int t = bid - 64;
        gemm_tile(x1, W_w, W_b, g_m1, FD, (t & 31) * RT, (t >> 5) * CT, sm);
    } else {
        lists_block(ve, bid - 128);
    }
}

// Mixed phase (448 blocks): [0,256) maskmax (L2-latency-bound) overlapped
// with [256,448) gh GEMM (FFMA-bound) — independent work, complementary pipes.
__global__ void __launch_bounds__(256, 3) k_mix(
    const float* __restrict__ x1,
    const float* __restrict__ whh, const float* __restrict__ bhh)
{
    extern __shared__ float sm[];
    int bid = blockIdx.x;
    if (bid < 256) {
        maskmax_block(bid);
    } else {
        int t = bid - 256;
        gemm_tile(x1, whh, bhh, g_gh, 3 * FD, (t & 31) * RT, (t >> 5) * CT, sm);
    }
}

// gi = x @ wih^T + bih  (64x64 tiles, occ 3 — R7 proven)
__global__ void __launch_bounds__(256, 3) k_gemmGI(
    const float* __restrict__ wih, const float* __restrict__ bih)
{
    extern __shared__ float sm[];
    gemm_tile(g_x, wih, bih, g_gi, 3 * FD, blockIdx.x * RT, blockIdx.y * CT, sm);
}

// ---------------- GRU gates (fast approx, float4) --------------------------
__device__ __forceinline__ float sigf(float t) {
    return __fdividef(1.0f, 1.0f + __expf(-t));
}
__device__ __forceinline__ float tanh_approx(float t) {
    float y;
    asm("tanh.approx.f32 %0, %1;" : "=f"(y) : "f"(t));
    return y;
}

__global__ void __launch_bounds__(128) k_gates(
    const float* __restrict__ x1, float* __restrict__ out)
{
    int idx = blockIdx.x * 128 + threadIdx.x;   // one float4 (4 feats)
    int row = idx >> 5, fq = idx & 31;
    const float4* gi = (const float4*)(g_gi + (size_t)row * 384);
    const float4* gh = (const float4*)(g_gh + (size_t)row * 384);
    float4 ir = __ldg(gi + fq);
    float4 iz = __ldg(gi + 32 + fq);
    float4 in_ = __ldg(gi + 64 + fq);
    float4 hr = __ldg(gh + fq);
    float4 hz = __ldg(gh + 32 + fq);
    float4 hn = __ldg(gh + 64 + fq);
    float4 hp = __ldg((const float4*)x1 + idx);
    float4 o;
    {
        float r = sigf(ir.x + hr.x), z = sigf(iz.x + hz.x);
        float n = tanh_approx(in_.x + r * hn.x);
        o.x = (1.0f - z) * n + z * hp.x;
    }
    {
        float r = sigf(ir.y + hr.y), z = sigf(iz.y + hz.y);
        float n = tanh_approx(in_.y + r * hn.y);
        o.y = (1.0f - z) * n + z * hp.y;
    }
    {
        float r = sigf(ir.z + hr.z), z = sigf(iz.z + hz.z);
        float n = tanh_approx(in_.z + r * hn.z);
        o.z = (1.0f - z) * n + z * hp.z;
    }
    {
        float r = sigf(ir.w + hr.w), z = sigf(iz.w + hz.w);
        float n = tanh_approx(in_.w + r * hn.w);
        o.w = (1.0f - z) * n + z * hp.w;
    }
    ((float4*)out)[idx] = o;
}

// ---------------- launch ---------------------------------------------------
extern "C" void kernel_launch(void* const* d_in, const int* in_sizes, int n_in,
                              void* d_out, int out_size)
{
    const float* x1  = (const float*)d_in[0];
    const float* x2  = (const float*)d_in[1];
    const float* ve  = (const float*)d_in[2];
    const float* W_w = (const float*)d_in[3];
    const float* W_b = (const float*)d_in[4];
    const float* M_w = (const float*)d_in[5];
    const float* M_b = (const float*)d_in[6];
    const float* wih = (const float*)d_in[7];
    const float* whh = (const float*)d_in[8];
    const float* bih = (const float*)d_in[9];
    const float* bhh = (const float*)d_in[10];
    float* out = (float*)d_out;

    const int smem = 2 * KD * LDT * (int)sizeof(float);   // 69632 B
    cudaFuncSetAttribute(k_p1a,    cudaFuncAttributeMaxDynamicSharedMemorySize, smem);
    cudaFuncSetAttribute(k_mix,    cudaFuncAttributeMaxDynamicSharedMemorySize, smem);
    cudaFuncSetAttribute(k_gemmGI, cudaFuncAttributeMaxDynamicSharedMemorySize, smem);

    k_p1a<<<384, 256, smem>>>(x1, x2, ve, W_w, W_b, M_w, M_b);
    k_mix<<<448, 256, smem>>>(x1, whh, bhh);
    k_gemmGI<<<dim3(ROWS / RT, 6), 256, smem>>>(wih, bih);
    k_gates<<<(ROWS * FD / 4) / 128, 128>>>(x1, out);
}

// round 12
// speedup vs baseline: 1.5463x; 1.2533x over previous
#include <cuda_runtime.h>
#include <math.h>
#include <float.h>

// Problem dims
#define Bn   8
#define N1D  256
#define N2D  256
#define FD   128
#define ROWS (Bn * N1D)          // 2048
#define KD   128

// GEMM tiling: 64x64 tile per 256-thread CTA; tf32 mma.sync inner loop.
#define RT  64
#define CT  64
#define LDT 68                   // padded minor dim of [k][*] smem tiles

// ---------------- device scratch (no allocations allowed) ----------------
__device__ float g_Mx2[Bn * N2D * FD];       // M(x2)            [2048,128]
__device__ float g_m1 [ROWS * FD];           // W(x1)            [2048,128]
__device__ float g_gh [ROWS * 3 * FD];       // x1 @ whh^T + bhh [2048,384]
__device__ float g_x  [ROWS * FD];           // relu(m1+m2)      [2048,128]
__device__ float g_gi [ROWS * 3 * FD];       // x @ wih^T + bih  [2048,384]
__device__ int   g_cnt [ROWS];               // valid-edge counts
__device__ int   g_list[ROWS * N2D];         // valid-edge j lists

// ---------------- tf32 helpers ---------------------------------------------
__device__ __forceinline__ unsigned tf32_of(float v) {
    unsigned u;
    asm("cvt.rna.tf32.f32 %0, %1;" : "=r"(u) : "f"(v));
    return u;
}

__device__ __forceinline__ void mma_tf32(float c[4],
                                         const unsigned a[4],
                                         const unsigned bf[2])
{
    asm("mma.sync.aligned.m16n8k8.row.col.f32.tf32.tf32.f32 "
        "{%0,%1,%2,%3}, {%4,%5,%6,%7}, {%8,%9}, {%0,%1,%2,%3};"
        : "+f"(c[0]), "+f"(c[1]), "+f"(c[2]), "+f"(c[3])
        : "r"(a[0]), "r"(a[1]), "r"(a[2]), "r"(a[3]),
          "r"(bf[0]), "r"(bf[1]));
}

// ---------------- 64x64 GEMM tile via tf32 tensor cores --------------------
// C[r,c] = sum_k A[r,k]*W[c,k] + b[c].
// Smem: As/Ws K-major [k][entity] (tf32-converted), staging = R7 proven
// conflict-free pattern. Warp w computes rows [(w&1)*32,+32) x cols
// [(w>>1)*16,+16) with 2x2 m16n8k8 fragments, 16 k-steps.
__device__ __forceinline__ void gemm_tile(
    const float* __restrict__ A, const float* __restrict__ W,
    const float* __restrict__ b,
    float* __restrict__ C, int ldC, int rowbase, int colbase, float* sm)
{
    unsigned* As = (unsigned*)sm;             // [KD][LDT]
    unsigned* Ws = (unsigned*)sm + KD * LDT;  // [KD][LDT]
    const int tid  = threadIdx.x;
    const int lane = tid & 31, warp = tid >> 5;
    const int kq = lane & 3;
    const int rr = lane >> 2;
    const int r  = warp * 8 + rr;     // 0..63

    // Stage + convert to tf32 (same address pattern as R7 scalar version).
#pragma unroll
    for (int it = 0; it < 8; it++) {
        int kk = it * 4 + kq;
        float4 av = *(const float4*)(A + (size_t)(rowbase + r) * KD + kk * 4);
        As[(kk * 4 + 0) * LDT + r] = tf32_of(av.x);
        As[(kk * 4 + 1) * LDT + r] = tf32_of(av.y);
        As[(kk * 4 + 2) * LDT + r] = tf32_of(av.z);
        As[(kk * 4 + 3) * LDT + r] = tf32_of(av.w);
        float4 wv = *(const float4*)(W + (size_t)(colbase + r) * KD + kk * 4);
        Ws[(kk * 4 + 0) * LDT + r] = tf32_of(wv.x);
        Ws[(kk * 4 + 1) * LDT + r] = tf32_of(wv.y);
        Ws[(kk * 4 + 2) * LDT + r] = tf32_of(wv.z);
        Ws[(kk * 4 + 3) * LDT + r] = tf32_of(wv.w);
    }
    __syncthreads();

    const int g   = lane >> 2;        // 0..7
    const int tig = lane & 3;         // 0..3
    const int wrow = (warp & 1) * 32;
    const int wcol = (warp >> 1) * 16;

    float c[2][2][4];                 // [mtile][ntile][frag]
#pragma unroll
    for (int i = 0; i < 2; i++)
#pragma unroll
        for (int j = 0; j < 2; j++)
#pragma unroll
            for (int q = 0; q < 4; q++) c[i][j][q] = 0.0f;

#pragma unroll
    for (int kb = 0; kb < KD; kb += 8) {
        const unsigned* Ak0 = As + (kb + tig) * LDT;
        const unsigned* Ak4 = Ak0 + 4 * LDT;
        const unsigned* Wk0 = Ws + (kb + tig) * LDT;
        const unsigned* Wk4 = Wk0 + 4 * LDT;

        unsigned a[2][4];
#pragma unroll
        for (int i = 0; i < 2; i++) {
            int base = wrow + i * 16 + g;
            a[i][0] = Ak0[base];
            a[i][1] = Ak0[base + 8];
            a[i][2] = Ak4[base];
            a[i][3] = Ak4[base + 8];
        }
        unsigned bf[2][2];
#pragma unroll
        for (int j = 0; j < 2; j++) {
            int base = wcol + j * 8 + g;
            bf[j][0] = Wk0[base];
            bf[j][1] = Wk4[base];
        }
#pragma unroll
        for (int i = 0; i < 2; i++)
#pragma unroll
            for (int j = 0; j < 2; j++)
                mma_tf32(c[i][j], a[i], bf[j]);
    }

    // Epilogue: c0,c1 -> (row g, cols 2tig,2tig+1); c2,c3 -> row g+8.
#pragma unroll
    for (int i = 0; i < 2; i++) {
#pragma unroll
        for (int j = 0; j < 2; j++) {
            int col = colbase + wcol + j * 8 + 2 * tig;
            float2 bv = *(const float2*)(b + col);
            int row0 = rowbase + wrow + i * 16 + g;
            float2 o0 = make_float2(c[i][j][0] + bv.x, c[i][j][1] + bv.y);
            *(float2*)(C + (size_t)row0 * ldC + col) = o0;
            float2 o1 = make_float2(c[i][j][2] + bv.x, c[i][j][3] + bv.y);
            *(float2*)(C + (size_t)(row0 + 8) * ldC + col) = o1;
        }
    }
}

// Edge-list compaction for 8 rows (one warp per row).
__device__ __forceinline__ void lists_block(const float* __restrict__ ve, int rowblock)
{
    int w = threadIdx.x >> 5, lane = threadIdx.x & 31;
    int row = rowblock * 8 + w;
    const float* mrow = ve + (size_t)row * N2D;
    int base = 0;
#pragma unroll
    for (int r = 0; r < 8; r++) {
        int j = r * 32 + lane;
        float v = mrow[j];
        unsigned bal = __ballot_sync(0xffffffffu, v != 0.0f);
        if (v != 0.0f)
            g_list[(size_t)row * N2D + base + __popc(bal & ((1u << lane) - 1u))] = j;
        base += __popc(bal);
    }
    if (lane == 0) g_cnt[row] = base;
}

// Phase 1 (576 blocks): [0,64) Mx2, [64,128) m1, [128,320) gh, [320,576) lists
__global__ void __launch_bounds__(256, 3) k_p1(
    const float* __restrict__ x1, const float* __restrict__ x2,
    const float* __restrict__ ve,
    const float* __restrict__ W_w, const float* __restrict__ W_b,
    const float* __restrict__ M_w, const float* __restrict__ M_b,
    const float* __restrict__ whh, const float* __restrict__ bhh)
{
    extern __shared__ float sm[];
    int bid = blockIdx.x;
    if (bid < 64) {
        gemm_tile(x2, M_w, M_b, g_Mx2, FD, (bid & 31) * RT, (bid >> 5) * CT, sm);
    } else if (bid < 128) {
        int t = bid - 64;
        gemm_tile(x1, W_w, W_b, g_m1, FD, (t & 31) * RT, (t >> 5) * CT, sm);
    } else if (bid < 320) {
        int t = bid - 128;
        gemm_tile(x1, whh, bhh, g_gh, 3 * FD, (t & 31) * RT, (t >> 5) * CT, sm);
    } else {
        lists_block(ve, bid - 320);
    }
}

// gi = x @ wih^T + bih
__global__ void __launch_bounds__(256, 3) k_gemmGI(
    const float* __restrict__ wih, const float* __restrict__ bih)
{
    extern __shared__ float sm[];
    gemm_tile(g_x, wih, bih, g_gi, 3 * FD, blockIdx.x * RT, blockIdx.y * CT, sm);
}

// ---------------- sparse masked max + relu(m1 + m2) — R7 proven ------------
__device__ __forceinline__ float4 max4(float4 a, float4 b) {
    float4 r;
    r.x = fmaxf(a.x, b.x); r.y = fmaxf(a.y, b.y);
    r.z = fmaxf(a.z, b.z); r.w = fmaxf(a.w, b.w);
    return r;
}

__global__ void __launch_bounds__(256) k_maskmax()
{
    int warp = threadIdx.x >> 5, lane = threadIdx.x & 31;
    int row = blockIdx.x * 8 + warp;
    int b = row >> 8;
    const float4* __restrict__ Mb = (const float4*)(g_Mx2 + (size_t)b * N2D * FD);
    const int* __restrict__ lst = g_list + (size_t)row * N2D;
    int cnt = g_cnt[row];

    float4 m = make_float4(-FLT_MAX, -FLT_MAX, -FLT_MAX, -FLT_MAX);
    int t = 0;
    for (; t + 4 <= cnt; t += 4) {
        int j0 = __ldg(lst + t),     j1 = __ldg(lst + t + 1);
        int j2 = __ldg(lst + t + 2), j3 = __ldg(lst + t + 3);
        float4 v0 = Mb[j0 * 32 + lane];
        float4 v1 = Mb[j1 * 32 + lane];
        float4 v2 = Mb[j2 * 32 + lane];
        float4 v3 = Mb[j3 * 32 + lane];
        m = max4(m, max4(max4(v0, v1), max4(v2, v3)));
    }
    for (; t < cnt; t++)
        m = max4(m, Mb[__ldg(lst + t) * 32 + lane]);
    if (cnt < N2D) {
        float4 z = make_float4(0.f, 0.f, 0.f, 0.f);
        m = max4(m, z);
    }
    float4 m1v = ((const float4*)g_m1)[row * 32 + lane];
    float4 x;
    x.x = fmaxf(m1v.x + m.x, 0.f);
    x.y = fmaxf(m1v.y + m.y, 0.f);
    x.z = fmaxf(m1v.z + m.z, 0.f);
    x.w = fmaxf(m1v.w + m.w, 0.f);
    ((float4*)g_x)[row * 32 + lane] = x;
}

// ---------------- GRU gates (fast approx, float4) --------------------------
__device__ __forceinline__ float sigf(float t) {
    return __fdividef(1.0f, 1.0f + __expf(-t));
}
__device__ __forceinline__ float tanh_approx(float t) {
    float y;
    asm("tanh.approx.f32 %0, %1;" : "=f"(y) : "f"(t));
    return y;
}

__global__ void __launch_bounds__(128) k_gates(
    const float* __restrict__ x1, float* __restrict__ out)
{
    int idx = blockIdx.x * 128 + threadIdx.x;   // one float4 (4 feats)
    int row = idx >> 5, fq = idx & 31;
    const float4* gi = (const float4*)(g_gi + (size_t)row * 384);
    const float4* gh = (const float4*)(g_gh + (size_t)row * 384);
    float4 ir = __ldg(gi + fq);
    float4 iz = __ldg(gi + 32 + fq);
    float4 in_ = __ldg(gi + 64 + fq);
    float4 hr = __ldg(gh + fq);
    float4 hz = __ldg(gh + 32 + fq);
    float4 hn = __ldg(gh + 64 + fq);
    float4 hp = __ldg((const float4*)x1 + idx);
    float4 o;
    {
        float r = sigf(ir.x + hr.x), z = sigf(iz.x + hz.x);
        float n = tanh_approx(in_.x + r * hn.x);
        o.x = (1.0f - z) * n + z * hp.x;
    }
    {
        float r = sigf(ir.y + hr.y), z = sigf(iz.y + hz.y);
        float n = tanh_approx(in_.y + r * hn.y);
        o.y = (1.0f - z) * n + z * hp.y;
    }
    {
        float r = sigf(ir.z + hr.z), z = sigf(iz.z + hz.z);
        float n = tanh_approx(in_.z + r * hn.z);
        o.z = (1.0f - z) * n + z * hp.z;
    }
    {
        float r = sigf(ir.w + hr.w), z = sigf(iz.w + hz.w);
        float n = tanh_approx(in_.w + r * hn.w);
        o.w = (1.0f - z) * n + z * hp.w;
    }
    ((float4*)out)[idx] = o;
}

// ---------------- launch ---------------------------------------------------
extern "C" void kernel_launch(void* const* d_in, const int* in_sizes, int n_in,
                              void* d_out, int out_size)
{
    const float* x1  = (const float*)d_in[0];
    const float* x2  = (const float*)d_in[1];
    const float* ve  = (const float*)d_in[2];
    const float* W_w = (const float*)d_in[3];
    const float* W_b = (const float*)d_in[4];
    const float* M_w = (const float*)d_in[5];
    const float* M_b = (const float*)d_in[6];
    const float* wih = (const float*)d_in[7];
    const float* whh = (const float*)d_in[8];
    const float* bih = (const float*)d_in[9];
    const float* bhh = (const float*)d_in[10];
    float* out = (float*)d_out;

    const int smem = 2 * KD * LDT * (int)sizeof(float);   // 69632 B
    cudaFuncSetAttribute(k_p1,     cudaFuncAttributeMaxDynamicSharedMemorySize, smem);
    cudaFuncSetAttribute(k_gemmGI, cudaFuncAttributeMaxDynamicSharedMemorySize, smem);

    k_p1<<<576, 256, smem>>>(x1, x2, ve, W_w, W_b, M_w, M_b, whh, bhh);
    k_maskmax<<<ROWS / 8, 256>>>();
    k_gemmGI<<<dim3(ROWS / RT, 6), 256, smem>>>(wih, bih);
    k_gates<<<(ROWS * FD / 4) / 128, 128>>>(x1, out);
}

// round 13
// speedup vs baseline: 1.5574x; 1.0072x over previous
#include <cuda_runtime.h>
#include <math.h>
#include <float.h>

// Problem dims
#define Bn   8
#define N1D  256
#define N2D  256
#define FD   128
#define ROWS (Bn * N1D)          // 2048
#define KD   128

// GEMM tiling: 64x64 tile per 256-thread CTA; tf32 mma.sync inner loop.
#define RT  64
#define CT  64
#define LDT 68                   // padded minor dim of [k][*] smem tiles

// ---------------- device scratch (no allocations allowed) ----------------
__device__ float g_Mx2[Bn * N2D * FD];       // M(x2)            [2048,128]
__device__ float g_m1 [ROWS * FD];           // W(x1)            [2048,128]
__device__ float g_gh [ROWS * 3 * FD];       // x1 @ whh^T + bhh [2048,384]
__device__ float g_x  [ROWS * FD];           // relu(m1+m2)      [2048,128]
__device__ float g_gi [ROWS * 3 * FD];       // x @ wih^T + bih  [2048,384]
__device__ int   g_cnt [ROWS];               // valid-edge counts
__device__ int   g_list[ROWS * N2D];         // valid-edge j lists

// ---------------- tf32 helpers ---------------------------------------------
__device__ __forceinline__ unsigned tf32_of(float v) {
    unsigned u;
    asm("cvt.rna.tf32.f32 %0, %1;" : "=r"(u) : "f"(v));
    return u;
}

__device__ __forceinline__ void mma_tf32(float c[4],
                                         const unsigned a[4],
                                         const unsigned bf[2])
{
    asm("mma.sync.aligned.m16n8k8.row.col.f32.tf32.tf32.f32 "
        "{%0,%1,%2,%3}, {%4,%5,%6,%7}, {%8,%9}, {%0,%1,%2,%3};"
        : "+f"(c[0]), "+f"(c[1]), "+f"(c[2]), "+f"(c[3])
        : "r"(a[0]), "r"(a[1]), "r"(a[2]), "r"(a[3]),
          "r"(bf[0]), "r"(bf[1]));
}

// ---------------- 64x64 GEMM tile via tf32 tensor cores --------------------
__device__ __forceinline__ void gemm_tile(
    const float* __restrict__ A, const float* __restrict__ W,
    const float* __restrict__ b,
    float* __restrict__ C, int ldC, int rowbase, int colbase, float* sm)
{
    unsigned* As = (unsigned*)sm;             // [KD][LDT]
    unsigned* Ws = (unsigned*)sm + KD * LDT;  // [KD][LDT]
    const int tid  = threadIdx.x;
    const int lane = tid & 31, warp = tid >> 5;
    const int kq = lane & 3;
    const int rr = lane >> 2;
    const int r  = warp * 8 + rr;     // 0..63

#pragma unroll
    for (int it = 0; it < 8; it++) {
        int kk = it * 4 + kq;
        float4 av = *(const float4*)(A + (size_t)(rowbase + r) * KD + kk * 4);
        As[(kk * 4 + 0) * LDT + r] = tf32_of(av.x);
        As[(kk * 4 + 1) * LDT + r] = tf32_of(av.y);
        As[(kk * 4 + 2) * LDT + r] = tf32_of(av.z);
        As[(kk * 4 + 3) * LDT + r] = tf32_of(av.w);
        float4 wv = *(const float4*)(W + (size_t)(colbase + r) * KD + kk * 4);
        Ws[(kk * 4 + 0) * LDT + r] = tf32_of(wv.x);
        Ws[(kk * 4 + 1) * LDT + r] = tf32_of(wv.y);
        Ws[(kk * 4 + 2) * LDT + r] = tf32_of(wv.z);
        Ws[(kk * 4 + 3) * LDT + r] = tf32_of(wv.w);
    }
    __syncthreads();

    const int g   = lane >> 2;        // 0..7
    const int tig = lane & 3;         // 0..3
    const int wrow = (warp & 1) * 32;
    const int wcol = (warp >> 1) * 16;

    float c[2][2][4];
#pragma unroll
    for (int i = 0; i < 2; i++)
#pragma unroll
        for (int j = 0; j < 2; j++)
#pragma unroll
            for (int q = 0; q < 4; q++) c[i][j][q] = 0.0f;

#pragma unroll
    for (int kb = 0; kb < KD; kb += 8) {
        const unsigned* Ak0 = As + (kb + tig) * LDT;
        const unsigned* Ak4 = Ak0 + 4 * LDT;
        const unsigned* Wk0 = Ws + (kb + tig) * LDT;
        const unsigned* Wk4 = Wk0 + 4 * LDT;

        unsigned a[2][4];
#pragma unroll
        for (int i = 0; i < 2; i++) {
            int base = wrow + i * 16 + g;
            a[i][0] = Ak0[base];
            a[i][1] = Ak0[base + 8];
            a[i][2] = Ak4[base];
            a[i][3] = Ak4[base + 8];
        }
        unsigned bf[2][2];
#pragma unroll
        for (int j = 0; j < 2; j++) {
            int base = wcol + j * 8 + g;
            bf[j][0] = Wk0[base];
            bf[j][1] = Wk4[base];
        }
#pragma unroll
        for (int i = 0; i < 2; i++)
#pragma unroll
            for (int j = 0; j < 2; j++)
                mma_tf32(c[i][j], a[i], bf[j]);
    }

#pragma unroll
    for (int i = 0; i < 2; i++) {
#pragma unroll
        for (int j = 0; j < 2; j++) {
            int col = colbase + wcol + j * 8 + 2 * tig;
            float2 bv = *(const float2*)(b + col);
            int row0 = rowbase + wrow + i * 16 + g;
            float2 o0 = make_float2(c[i][j][0] + bv.x, c[i][j][1] + bv.y);
            *(float2*)(C + (size_t)row0 * ldC + col) = o0;
            float2 o1 = make_float2(c[i][j][2] + bv.x, c[i][j][3] + bv.y);
            *(float2*)(C + (size_t)(row0 + 8) * ldC + col) = o1;
        }
    }
}

// Edge-list compaction for 8 rows (one warp per row).
__device__ __forceinline__ void lists_block(const float* __restrict__ ve, int rowblock)
{
    int w = threadIdx.x >> 5, lane = threadIdx.x & 31;
    int row = rowblock * 8 + w;
    const float* mrow = ve + (size_t)row * N2D;
    int base = 0;
#pragma unroll
    for (int r = 0; r < 8; r++) {
        int j = r * 32 + lane;
        float v = mrow[j];
        unsigned bal = __ballot_sync(0xffffffffu, v != 0.0f);
        if (v != 0.0f)
            g_list[(size_t)row * N2D + base + __popc(bal & ((1u << lane) - 1u))] = j;
        base += __popc(bal);
    }
    if (lane == 0) g_cnt[row] = base;
}

// Phase 1 (576 blocks): [0,64) Mx2, [64,128) m1, [128,320) gh, [320,576) lists
__global__ void __launch_bounds__(256, 3) k_p1(
    const float* __restrict__ x1, const float* __restrict__ x2,
    const float* __restrict__ ve,
    const float* __restrict__ W_w, const float* __restrict__ W_b,
    const float* __restrict__ M_w, const float* __restrict__ M_b,
    const float* __restrict__ whh, const float* __restrict__ bhh)
{
    extern __shared__ float sm[];
    int bid = blockIdx.x;
    if (bid < 64) {
        gemm_tile(x2, M_w, M_b, g_Mx2, FD, (bid & 31) * RT, (bid >> 5) * CT, sm);
    } else if (bid < 128) {
        int t = bid - 64;
        gemm_tile(x1, W_w, W_b, g_m1, FD, (t & 31) * RT, (t >> 5) * CT, sm);
    } else if (bid < 320) {
        int t = bid - 128;
        gemm_tile(x1, whh, bhh, g_gh, 3 * FD, (t & 31) * RT, (t >> 5) * CT, sm);
    } else {
        lists_block(ve, bid - 320);
    }
}

// gi = x @ wih^T + bih
__global__ void __launch_bounds__(256, 3) k_gemmGI(
    const float* __restrict__ wih, const float* __restrict__ bih)
{
    extern __shared__ float sm[];
    gemm_tile(g_x, wih, bih, g_gi, 3 * FD, blockIdx.x * RT, blockIdx.y * CT, sm);
}

// ---------------- sparse masked max + relu(m1 + m2) — R7 proven ------------
__device__ __forceinline__ float4 max4(float4 a, float4 b) {
    float4 r;
    r.x = fmaxf(a.x, b.x); r.y = fmaxf(a.y, b.y);
    r.z = fmaxf(a.z, b.z); r.w = fmaxf(a.w, b.w);
    return r;
}

__global__ void __launch_bounds__(256) k_maskmax()
{
    int warp = threadIdx.x >> 5, lane = threadIdx.x & 31;
    int row = blockIdx.x * 8 + warp;
    int b = row >> 8;
    const float4* __restrict__ Mb = (const float4*)(g_Mx2 + (size_t)b * N2D * FD);
    const int* __restrict__ lst = g_list + (size_t)row * N2D;
    int cnt = g_cnt[row];

    float4 m = make_float4(-FLT_MAX, -FLT_MAX, -FLT_MAX, -FLT_MAX);
    int t = 0;
    for (; t + 4 <= cnt; t += 4) {
        int j0 = __ldg(lst + t),     j1 = __ldg(lst + t + 1);
        int j2 = __ldg(lst + t + 2), j3 = __ldg(lst + t + 3);
        float4 v0 = Mb[j0 * 32 + lane];
        float4 v1 = Mb[j1 * 32 + lane];
        float4 v2 = Mb[j2 * 32 + lane];
        float4 v3 = Mb[j3 * 32 + lane];
        m = max4(m, max4(max4(v0, v1), max4(v2, v3)));
    }
    for (; t < cnt; t++)
        m = max4(m, Mb[__ldg(lst + t) * 32 + lane]);
    if (cnt < N2D) {
        float4 z = make_float4(0.f, 0.f, 0.f, 0.f);
        m = max4(m, z);
    }
    float4 m1v = ((const float4*)g_m1)[row * 32 + lane];
    float4 x;
    x.x = fmaxf(m1v.x + m.x, 0.f);
    x.y = fmaxf(m1v.y + m.y, 0.f);
    x.z = fmaxf(m1v.z + m.z, 0.f);
    x.w = fmaxf(m1v.w + m.w, 0.f);
    ((float4*)g_x)[row * 32 + lane] = x;
}

// ---------------- GRU gates (tanh-only approx: 3 MUFU / element) -----------
__device__ __forceinline__ float tanh_approx(float t) {
    float y;
    asm("tanh.approx.f32 %0, %1;" : "=f"(y) : "f"(t));
    return y;
}
// sigmoid(x) = 0.5 + 0.5*tanh(x/2) — single MUFU, no RCP dependency.
__device__ __forceinline__ float sigf(float t) {
    return fmaf(tanh_approx(0.5f * t), 0.5f, 0.5f);
}

__global__ void __launch_bounds__(128) k_gates(
    const float* __restrict__ x1, float* __restrict__ out)
{
    int idx = blockIdx.x * 128 + threadIdx.x;   // one float4 (4 feats)
    int row = idx >> 5, fq = idx & 31;
    const float4* gi = (const float4*)(g_gi + (size_t)row * 384);
    const float4* gh = (const float4*)(g_gh + (size_t)row * 384);
    float4 ir = __ldg(gi + fq);
    float4 iz = __ldg(gi + 32 + fq);
    float4 in_ = __ldg(gi + 64 + fq);
    float4 hr = __ldg(gh + fq);
    float4 hz = __ldg(gh + 32 + fq);
    float4 hn = __ldg(gh + 64 + fq);
    float4 hp = __ldg((const float4*)x1 + idx);
    float4 o;
    {
        float r = sigf(ir.x + hr.x), z = sigf(iz.x + hz.x);
        float n = tanh_approx(in_.x + r * hn.x);
        o.x = (1.0f - z) * n + z * hp.x;
    }
    {
        float r = sigf(ir.y + hr.y), z = sigf(iz.y + hz.y);
        float n = tanh_approx(in_.y + r * hn.y);
        o.y = (1.0f - z) * n + z * hp.y;
    }
    {
        float r = sigf(ir.z + hr.z), z = sigf(iz.z + hz.z);
        float n = tanh_approx(in_.z + r * hn.z);
        o.z = (1.0f - z) * n + z * hp.z;
    }
    {
        float r = sigf(ir.w + hr.w), z = sigf(iz.w + hz.w);
        float n = tanh_approx(in_.w + r * hn.w);
        o.w = (1.0f - z) * n + z * hp.w;
    }
    ((float4*)out)[idx] = o;
}

// ---------------- launch ---------------------------------------------------
extern "C" void kernel_launch(void* const* d_in, const int* in_sizes, int n_in,
                              void* d_out, int out_size)
{
    const float* x1  = (const float*)d_in[0];
    const float* x2  = (const float*)d_in[1];
    const float* ve  = (const float*)d_in[2];
    const float* W_w = (const float*)d_in[3];
    const float* W_b = (const float*)d_in[4];
    const float* M_w = (const float*)d_in[5];
    const float* M_b = (const float*)d_in[6];
    const float* wih = (const float*)d_in[7];
    const float* whh = (const float*)d_in[8];
    const float* bih = (const float*)d_in[9];
    const float* bhh = (const float*)d_in[10];
    float* out = (float*)d_out;

    const int smem = 2 * KD * LDT * (int)sizeof(float);   // 69632 B
    cudaFuncSetAttribute(k_p1,     cudaFuncAttributeMaxDynamicSharedMemorySize, smem);
    cudaFuncSetAttribute(k_gemmGI, cudaFuncAttributeMaxDynamicSharedMemorySize, smem);

    k_p1<<<576, 256, smem>>>(x1, x2, ve, W_w, W_b, M_w, M_b, whh, bhh);
    k_maskmax<<<ROWS / 8, 256>>>();
    k_gemmGI<<<dim3(ROWS / RT, 6), 256, smem>>>(wih, bih);
    k_gates<<<(ROWS * FD / 4) / 128, 128>>>(x1, out);
}

// round 14
// speedup vs baseline: 1.5590x; 1.0010x over previous
#include <cuda_runtime.h>
#include <math.h>
#include <float.h>

// Problem dims
#define Bn   8
#define N1D  256
#define N2D  256
#define FD   128
#define ROWS (Bn * N1D)          // 2048
#define KD   128

#define LDTW 68                  // padded minor dim, 64-entity tiles
#define LDA  132                 // padded minor dim, 128-entity A tiles

// ---------------- device scratch (no allocations allowed) ----------------
__device__ float g_Mx2[Bn * N2D * FD];       // M(x2)            [2048,128]
__device__ float g_m1 [ROWS * FD];           // W(x1)            [2048,128]
__device__ float g_gh [ROWS * 3 * FD];       // x1 @ whh^T + bhh [2048,384]
__device__ float g_x  [ROWS * FD];           // relu(m1+m2)      [2048,128]
__device__ float g_gi [ROWS * 3 * FD];       // x @ wih^T + bih  [2048,384]
__device__ int   g_cnt [ROWS];               // valid-edge counts
__device__ int   g_list[ROWS * N2D];         // valid-edge j lists

// ---------------- tf32 helpers ---------------------------------------------
__device__ __forceinline__ unsigned tf32_of(float v) {
    unsigned u;
    asm("cvt.rna.tf32.f32 %0, %1;" : "=r"(u) : "f"(v));
    return u;
}

__device__ __forceinline__ void mma_tf32(float c[4],
                                         const unsigned a[4],
                                         const unsigned bf[2])
{
    asm("mma.sync.aligned.m16n8k8.row.col.f32.tf32.tf32.f32 "
        "{%0,%1,%2,%3}, {%4,%5,%6,%7}, {%8,%9}, {%0,%1,%2,%3};"
        : "+f"(c[0]), "+f"(c[1]), "+f"(c[2]), "+f"(c[3])
        : "r"(a[0]), "r"(a[1]), "r"(a[2]), "r"(a[3]),
          "r"(bf[0]), "r"(bf[1]));
}

// ---------------- 128x64 GEMM tile (phase 1), warp tile 32x32 --------------
__device__ __forceinline__ void gemm_tile128(
    const float* __restrict__ A, const float* __restrict__ W,
    const float* __restrict__ b,
    float* __restrict__ C, int ldC, int rowbase, int colbase, float* sm)
{
    unsigned* As = (unsigned*)sm;              // [KD][LDA]   (128 rows)
    unsigned* Ws = (unsigned*)sm + KD * LDA;   // [KD][LDTW]  (64 cols)
    const int tid  = threadIdx.x;
    const int lane = tid & 31, warp = tid >> 5;
    const int kq = lane & 3;
    const int rr = lane >> 2;

    // Stage A (128 rows x 128 k), two 64-row halves per thread row slot.
#pragma unroll
    for (int half = 0; half < 2; half++) {
        int r = warp * 8 + rr + half * 64;
#pragma unroll
        for (int it = 0; it < 8; it++) {
            int kk = it * 4 + kq;
            float4 av = *(const float4*)(A + (size_t)(rowbase + r) * KD + kk * 4);
            As[(kk * 4 + 0) * LDA + r] = tf32_of(av.x);
            As[(kk * 4 + 1) * LDA + r] = tf32_of(av.y);
            As[(kk * 4 + 2) * LDA + r] = tf32_of(av.z);
            As[(kk * 4 + 3) * LDA + r] = tf32_of(av.w);
        }
    }
    // Stage W (64 cols x 128 k).
    {
        int r = warp * 8 + rr;
#pragma unroll
        for (int it = 0; it < 8; it++) {
            int kk = it * 4 + kq;
            float4 wv = *(const float4*)(W + (size_t)(colbase + r) * KD + kk * 4);
            Ws[(kk * 4 + 0) * LDTW + r] = tf32_of(wv.x);
            Ws[(kk * 4 + 1) * LDTW + r] = tf32_of(wv.y);
            Ws[(kk * 4 + 2) * LDTW + r] = tf32_of(wv.z);
            Ws[(kk * 4 + 3) * LDTW + r] = tf32_of(wv.w);
        }
    }
    __syncthreads();

    const int g   = lane >> 2;        // 0..7
    const int tig = lane & 3;         // 0..3
    const int wrow = (warp & 3) * 32; // 4 row groups x 32
    const int wcol = (warp >> 2) * 16 * 2;  // 2 col groups x 32

    float c[2][4][4];
#pragma unroll
    for (int i = 0; i < 2; i++)
#pragma unroll
        for (int j = 0; j < 4; j++)
#pragma unroll
            for (int q = 0; q < 4; q++) c[i][j][q] = 0.0f;

#pragma unroll
    for (int kb = 0; kb < KD; kb += 8) {
        const unsigned* Ak0 = As + (kb + tig) * LDA;
        const unsigned* Ak4 = Ak0 + 4 * LDA;
        const unsigned* Wk0 = Ws + (kb + tig) * LDTW;
        const unsigned* Wk4 = Wk0 + 4 * LDTW;

        unsigned a[2][4];
#pragma unroll
        for (int i = 0; i < 2; i++) {
            int base = wrow + i * 16 + g;
            a[i][0] = Ak0[base];
            a[i][1] = Ak0[base + 8];
            a[i][2] = Ak4[base];
            a[i][3] = Ak4[base + 8];
        }
        unsigned bf[4][2];
#pragma unroll
        for (int j = 0; j < 4; j++) {
            int nb = wcol + j * 8 + g;
            bf[j][0] = Wk0[nb];
            bf[j][1] = Wk4[nb];
        }
#pragma unroll
        for (int i = 0; i < 2; i++)
#pragma unroll
            for (int j = 0; j < 4; j++)
                mma_tf32(c[i][j], a[i], bf[j]);
    }

#pragma unroll
    for (int i = 0; i < 2; i++) {
#pragma unroll
        for (int j = 0; j < 4; j++) {
            int col = colbase + wcol + j * 8 + 2 * tig;
            float2 bv = *(const float2*)(b + col);
            int row0 = rowbase + wrow + i * 16 + g;
            float2 o0 = make_float2(c[i][j][0] + bv.x, c[i][j][1] + bv.y);
            *(float2*)(C + (size_t)row0 * ldC + col) = o0;
            float2 o1 = make_float2(c[i][j][2] + bv.x, c[i][j][3] + bv.y);
            *(float2*)(C + (size_t)(row0 + 8) * ldC + col) = o1;
        }
    }
}

// ---------------- 64x64 GEMM tile (R12 proven — used by gemmGI) ------------
__device__ __forceinline__ void gemm_tile(
    const float* __restrict__ A, const float* __restrict__ W,
    const float* __restrict__ b,
    float* __restrict__ C, int ldC, int rowbase, int colbase, float* sm)
{
    unsigned* As = (unsigned*)sm;              // [KD][LDTW]
    unsigned* Ws = (unsigned*)sm + KD * LDTW;  // [KD][LDTW]
    const int tid  = threadIdx.x;
    const int lane = tid & 31, warp = tid >> 5;
    const int kq = lane & 3;
    const int rr = lane >> 2;
    const int r  = warp * 8 + rr;     // 0..63

#pragma unroll
    for (int it = 0; it < 8; it++) {
        int kk = it * 4 + kq;
        float4 av = *(const float4*)(A + (size_t)(rowbase + r) * KD + kk * 4);
        As[(kk * 4 + 0) * LDTW + r] = tf32_of(av.x);
        As[(kk * 4 + 1) * LDTW + r] = tf32_of(av.y);
        As[(kk * 4 + 2) * LDTW + r] = tf32_of(av.z);
        As[(kk * 4 + 3) * LDTW + r] = tf32_of(av.w);
        float4 wv = *(const float4*)(W + (size_t)(colbase + r) * KD + kk * 4);
        Ws[(kk * 4 + 0) * LDTW + r] = tf32_of(wv.x);
        Ws[(kk * 4 + 1) * LDTW + r] = tf32_of(wv.y);
        Ws[(kk * 4 + 2) * LDTW + r] = tf32_of(wv.z);
        Ws[(kk * 4 + 3) * LDTW + r] = tf32_of(wv.w);
    }
    __syncthreads();

    const int g   = lane >> 2;
    const int tig = lane & 3;
    const int wrow = (warp & 1) * 32;
    const int wcol = (warp >> 1) * 16;

    float c[2][2][4];
#pragma unroll
    for (int i = 0; i < 2; i++)
#pragma unroll
        for (int j = 0; j < 2; j++)
#pragma unroll
            for (int q = 0; q < 4; q++) c[i][j][q] = 0.0f;

#pragma unroll
    for (int kb = 0; kb < KD; kb += 8) {
        const unsigned* Ak0 = As + (kb + tig) * LDTW;
        const unsigned* Ak4 = Ak0 + 4 * LDTW;
        const unsigned* Wk0 = Ws + (kb + tig) * LDTW;
        const unsigned* Wk4 = Wk0 + 4 * LDTW;

        unsigned a[2][4];
#pragma unroll
        for (int i = 0; i < 2; i++) {
            int base = wrow + i * 16 + g;
            a[i][0] = Ak0[base];
            a[i][1] = Ak0[base + 8];
            a[i][2] = Ak4[base];
            a[i][3] = Ak4[base + 8];
        }
        unsigned bf[2][2];
#pragma unroll
        for (int j = 0; j < 2; j++) {
            int base = wcol + j * 8 + g;
            bf[j][0] = Wk0[base];
            bf[j][1] = Wk4[base];
        }
#pragma unroll
        for (int i = 0; i < 2; i++)
#pragma unroll
            for (int j = 0; j < 2; j++)
                mma_tf32(c[i][j], a[i], bf[j]);
    }

#pragma unroll
    for (int i = 0; i < 2; i++) {
#pragma unroll
        for (int j = 0; j < 2; j++) {
            int col = colbase + wcol + j * 8 + 2 * tig;
            float2 bv = *(const float2*)(b + col);
            int row0 = rowbase + wrow + i * 16 + g;
            float2 o0 = make_float2(c[i][j][0] + bv.x, c[i][j][1] + bv.y);
            *(float2*)(C + (size_t)row0 * ldC + col) = o0;
            float2 o1 = make_float2(c[i][j][2] + bv.x, c[i][j][3] + bv.y);
            *(float2*)(C + (size_t)(row0 + 8) * ldC + col) = o1;
        }
    }
}

// Edge-list compaction for 8 rows (one warp per row).
__device__ __forceinline__ void lists_block(const float* __restrict__ ve, int rowblock)
{
    int w = threadIdx.x >> 5, lane = threadIdx.x & 31;
    int row = rowblock * 8 + w;
    const float* mrow = ve + (size_t)row * N2D;
    int base = 0;
#pragma unroll
    for (int r = 0; r < 8; r++) {
        int j = r * 32 + lane;
        float v = mrow[j];
        unsigned bal = __ballot_sync(0xffffffffu, v != 0.0f);
        if (v != 0.0f)
            g_list[(size_t)row * N2D + base + __popc(bal & ((1u << lane) - 1u))] = j;
        base += __popc(bal);
    }
    if (lane == 0) g_cnt[row] = base;
}

// Phase 1 (416 blocks): [0,32) Mx2, [32,64) m1, [64,160) gh, [160,416) lists.
// GEMM blocks use 128x64 tiles (16 row-tiles of 128 rows).
__global__ void __launch_bounds__(256, 2) k_p1(
    const float* __restrict__ x1, const float* __restrict__ x2,
    const float* __restrict__ ve,
    const float* __restrict__ W_w, const float* __restrict__ W_b,
    const float* __restrict__ M_w, const float* __restrict__ M_b,
    const float* __restrict__ whh, const float* __restrict__ bhh)
{
    extern __shared__ float sm[];
    int bid = blockIdx.x;
    if (bid < 32) {
        gemm_tile128(x2, M_w, M_b, g_Mx2, FD, (bid & 15) * 128, (bid >> 4) * 64, sm);
    } else if (bid < 64) {
        int t = bid - 32;
        gemm_tile128(x1, W_w, W_b, g_m1, FD, (t & 15) * 128, (t >> 4) * 64, sm);
    } else if (bid < 160) {
        int t = bid - 64;
        gemm_tile128(x1, whh, bhh, g_gh, 3 * FD, (t & 15) * 128, (t >> 4) * 64, sm);
    } else {
        lists_block(ve, bid - 160);
    }
}

// gi = x @ wih^T + bih  (64x64 tiles, occ 3 — proven)
__global__ void __launch_bounds__(256, 3) k_gemmGI(
    const float* __restrict__ wih, const float* __restrict__ bih)
{
    extern __shared__ float sm[];
    gemm_tile(g_x, wih, bih, g_gi, 3 * FD, blockIdx.x * 64, blockIdx.y * 64, sm);
}

// ---------------- sparse masked max + relu(m1 + m2) — R7 proven ------------
__device__ __forceinline__ float4 max4(float4 a, float4 b) {
    float4 r;
    r.x = fmaxf(a.x, b.x); r.y = fmaxf(a.y, b.y);
    r.z = fmaxf(a.z, b.z); r.w = fmaxf(a.w, b.w);
    return r;
}

__global__ void __launch_bounds__(256) k_maskmax()
{
    int warp = threadIdx.x >> 5, lane = threadIdx.x & 31;
    int row = blockIdx.x * 8 + warp;
    int b = row >> 8;
    const float4* __restrict__ Mb = (const float4*)(g_Mx2 + (size_t)b * N2D * FD);
    const int* __restrict__ lst = g_list + (size_t)row * N2D;
    int cnt = g_cnt[row];

    float4 m = make_float4(-FLT_MAX, -FLT_MAX, -FLT_MAX, -FLT_MAX);
    int t = 0;
    for (; t + 4 <= cnt; t += 4) {
        int j0 = __ldg(lst + t),     j1 = __ldg(lst + t + 1);
        int j2 = __ldg(lst + t + 2), j3 = __ldg(lst + t + 3);
        float4 v0 = Mb[j0 * 32 + lane];
        float4 v1 = Mb[j1 * 32 + lane];
        float4 v2 = Mb[j2 * 32 + lane];
        float4 v3 = Mb[j3 * 32 + lane];
        m = max4(m, max4(max4(v0, v1), max4(v2, v3)));
    }
    for (; t < cnt; t++)
        m = max4(m, Mb[__ldg(lst + t) * 32 + lane]);
    if (cnt < N2D) {
        float4 z = make_float4(0.f, 0.f, 0.f, 0.f);
        m = max4(m, z);
    }
    float4 m1v = ((const float4*)g_m1)[row * 32 + lane];
    float4 x;
    x.x = fmaxf(m1v.x + m.x, 0.f);
    x.y = fmaxf(m1v.y + m.y, 0.f);
    x.z = fmaxf(m1v.z + m.z, 0.f);
    x.w = fmaxf(m1v.w + m.w, 0.f);
    ((float4*)g_x)[row * 32 + lane] = x;
}

// ---------------- GRU gates (tanh-only approx) -----------------------------
__device__ __forceinline__ float tanh_approx(float t) {
    float y;
    asm("tanh.approx.f32 %0, %1;" : "=f"(y) : "f"(t));
    return y;
}
__device__ __forceinline__ float sigf(float t) {
    return fmaf(tanh_approx(0.5f * t), 0.5f, 0.5f);
}

__global__ void __launch_bounds__(128) k_gates(
    const float* __restrict__ x1, float* __restrict__ out)
{
    int idx = blockIdx.x * 128 + threadIdx.x;   // one float4 (4 feats)
    int row = idx >> 5, fq = idx & 31;
    const float4* gi = (const float4*)(g_gi + (size_t)row * 384);
    const float4* gh = (const float4*)(g_gh + (size_t)row * 384);
    float4 ir = __ldg(gi + fq);
    float4 iz = __ldg(gi + 32 + fq);
    float4 in_ = __ldg(gi + 64 + fq);
    float4 hr = __ldg(gh + fq);
    float4 hz = __ldg(gh + 32 + fq);
    float4 hn = __ldg(gh + 64 + fq);
    float4 hp = __ldg((const float4*)x1 + idx);
    float4 o;
    {
        float r = sigf(ir.x + hr.x), z = sigf(iz.x + hz.x);
        float n = tanh_approx(in_.x + r * hn.x);
        o.x = (1.0f - z) * n + z * hp.x;
    }
    {
        float r = sigf(ir.y + hr.y), z = sigf(iz.y + hz.y);
        float n = tanh_approx(in_.y + r * hn.y);
        o.y = (1.0f - z) * n + z * hp.y;
    }
    {
        float r = sigf(ir.z + hr.z), z = sigf(iz.z + hz.z);
        float n = tanh_approx(in_.z + r * hn.z);
        o.z = (1.0f - z) * n + z * hp.z;
    }
    {
        float r = sigf(ir.w + hr.w), z = sigf(iz.w + hz.w);
        float n = tanh_approx(in_.w + r * hn.w);
        o.w = (1.0f - z) * n + z * hp.w;
    }
    ((float4*)out)[idx] = o;
}

// ---------------- launch ---------------------------------------------------
extern "C" void kernel_launch(void* const* d_in, const int* in_sizes, int n_in,
                              void* d_out, int out_size)
{
    const float* x1  = (const float*)d_in[0];
    const float* x2  = (const float*)d_in[1];
    const float* ve  = (const float*)d_in[2];
    const float* W_w = (const float*)d_in[3];
    const float* W_b = (const float*)d_in[4];
    const float* M_w = (const float*)d_in[5];
    const float* M_b = (const float*)d_in[6];
    const float* wih = (const float*)d_in[7];
    const float* whh = (const float*)d_in[8];
    const float* bih = (const float*)d_in[9];
    const float* bhh = (const float*)d_in[10];
    float* out = (float*)d_out;

    const int smemP1 = KD * (LDA + LDTW) * (int)sizeof(float);   // 102400
    const int smemGI = 2 * KD * LDTW * (int)sizeof(float);       // 69632
    cudaFuncSetAttribute(k_p1,     cudaFuncAttributeMaxDynamicSharedMemorySize, smemP1);
    cudaFuncSetAttribute(k_gemmGI, cudaFuncAttributeMaxDynamicSharedMemorySize, smemGI);

    k_p1<<<416, 256, smemP1>>>(x1, x2, ve, W_w, W_b, M_w, M_b, whh, bhh);
    k_maskmax<<<ROWS / 8, 256>>>();
    k_gemmGI<<<dim3(ROWS / 64, 6), 256, smemGI>>>(wih, bih);
    k_gates<<<(ROWS * FD / 4) / 128, 128>>>(x1, out);
}